// round 13
// baseline (speedup 1.0000x reference)
#include <cuda_runtime.h>
#include <cuda_bf16.h>
#include <cuda_fp16.h>
#include <cstdint>

// Problem constants
#define B    64
#define T    512
#define DIN  256
#define H    512
#define G    2048   // 4*H

#define NCTA 128

// mma_gemm tile config (proven R8)
#define MG_BUF   24576
#define MG_SMEM  (2 * MG_BUF)

// recur_tc SMEM layout (bytes): Whi @0 | Wlo @32768 | Hf @65536 | part @98304
#define RT_PART_OFF 98304
#define RT_SMEM     (98304 + 4 * 32 * 34 * 4)   // 115712

// scale for the fp16 W lo-plane (avoids fp16 denormal flush)
#define WLO_SCALE    1024.0f
#define WLO_INV      (1.0f / 1024.0f)

typedef unsigned long long u64;

// ------------------------- device scratch -------------------------
__device__ float g_Whh0[G * H];
__device__ float g_Whh1[G * H];
__device__ float g_bias0[G];
__device__ float g_bias1[G];
__device__ float g_xW[(size_t)T * B * G];            // [t*B+b][G]
__device__ unsigned int g_bar2[2][16];
// bf16 hi/lo activations for PROJECTION GEMMs: x, then layer0 h-sequence
__device__ __nv_bfloat16 g_Ah[(size_t)T * B * H];
__device__ __nv_bfloat16 g_Al[(size_t)T * B * H];
// fp16 h planes for the RECURRENCE
__device__ __half g_Af16[(size_t)T * B * H];         // layer0 h sequence (fp16)
__device__ __half g_h1f16[2][B * H];                 // layer1 double-buffered h; [0] = t=0 zeros
// masked+split input-projection weights (bf16, proven path)
__device__ __nv_bfloat16 g_W0h[G * DIN], g_W0l[G * DIN];
__device__ __nv_bfloat16 g_W1h[G * H],   g_W1l[G * H];

// ------------------------- helpers -------------------------
__device__ __forceinline__ float sigmf(float x) {
    return 1.0f / (1.0f + __expf(-x));
}
__device__ __forceinline__ uint32_t smem_u32(const void* p) {
    uint32_t a;
    asm("{ .reg .u64 t; cvta.to.shared.u64 t, %1; cvt.u32.u64 %0, t; }" : "=r"(a) : "l"(p));
    return a;
}
__device__ __forceinline__ void ldsm4(uint32_t* r, uint32_t addr) {
    asm volatile("ldmatrix.sync.aligned.m8n8.x4.shared.b16 {%0,%1,%2,%3}, [%4];"
                 : "=r"(r[0]), "=r"(r[1]), "=r"(r[2]), "=r"(r[3]) : "r"(addr));
}
// bf16 HMMA (projection GEMM)
__device__ __forceinline__ void mma_bf16(float* d, const uint32_t* a, const uint32_t* b) {
    asm volatile(
        "mma.sync.aligned.m16n8k16.row.col.f32.bf16.bf16.f32 "
        "{%0,%1,%2,%3}, {%4,%5,%6,%7}, {%8,%9}, {%0,%1,%2,%3};"
        : "+f"(d[0]), "+f"(d[1]), "+f"(d[2]), "+f"(d[3])
        : "r"(a[0]), "r"(a[1]), "r"(a[2]), "r"(a[3]), "r"(b[0]), "r"(b[1]));
}
// fp16 HMMA (recurrence)
__device__ __forceinline__ void mma_f16(float* d, const uint32_t* a, const uint32_t* b) {
    asm volatile(
        "mma.sync.aligned.m16n8k16.row.col.f32.f16.f16.f32 "
        "{%0,%1,%2,%3}, {%4,%5,%6,%7}, {%8,%9}, {%0,%1,%2,%3};"
        : "+f"(d[0]), "+f"(d[1]), "+f"(d[2]), "+f"(d[3])
        : "r"(a[0]), "r"(a[1]), "r"(a[2]), "r"(a[3]), "r"(b[0]), "r"(b[1]));
}
__device__ __forceinline__ void st_u16_cg(void* p, unsigned short u) {
    asm volatile("st.global.cg.u16 [%0], %1;" :: "l"(p), "h"(u) : "memory");
}

// ------------------------- prep -------------------------
__global__ void prep_kernel(const float* Wih0, const float* mih0,
                            const float* Whh0, const float* mhh0,
                            const float* bih0, const float* bhh0,
                            const float* Wih1, const float* mih1,
                            const float* Whh1, const float* mhh1,
                            const float* bih1, const float* bhh1)
{
    int idx0 = blockIdx.x * blockDim.x + threadIdx.x;
    int stride = gridDim.x * blockDim.x;
    for (int i = idx0; i < G * H; i += stride) g_Whh0[i] = Whh0[i] * mhh0[i];
    for (int i = idx0; i < G * H; i += stride) g_Whh1[i] = Whh1[i] * mhh1[i];
    for (int i = idx0; i < G * DIN; i += stride) {
        float v = Wih0[i] * mih0[i];
        __nv_bfloat16 h = __float2bfloat16(v);
        g_W0h[i] = h;
        g_W0l[i] = __float2bfloat16(v - __bfloat162float(h));
    }
    for (int i = idx0; i < G * H; i += stride) {
        float v = Wih1[i] * mih1[i];
        __nv_bfloat16 h = __float2bfloat16(v);
        g_W1h[i] = h;
        g_W1l[i] = __float2bfloat16(v - __bfloat162float(h));
    }
    for (int i = idx0; i < G; i += stride) {
        g_bias0[i] = bih0[i] + bhh0[i];
        g_bias1[i] = bih1[i] + bhh1[i];
    }
}

__global__ void reset_state() {
    int i = blockIdx.x * blockDim.x + threadIdx.x;
    if (i < B * H) {
        __half z = __float2half(0.0f);
        g_h1f16[0][i] = z; g_h1f16[1][i] = z;
    }
    if (i < 32) g_bar2[i >> 4][i & 15] = 0u;
}

// convert x [B,T,DIN] -> bf16 hi/lo [t*B+b][DIN]
__global__ void convert_x(const float* __restrict__ x) {
    int i = blockIdx.x * blockDim.x + threadIdx.x;
    int n = T * B * DIN;
    for (; i < n; i += gridDim.x * blockDim.x) {
        int m = i / DIN, k = i - m * DIN;
        int b = m & (B - 1), t = m >> 6;
        float v = x[(size_t)(b * T + t) * DIN + k];
        __nv_bfloat16 h = __float2bfloat16(v);
        g_Ah[i] = h;
        g_Al[i] = __float2bfloat16(v - __bfloat162float(h));
    }
}

// ------------------------- warp-MMA projection GEMM (proven R8, bf16 3-term) -------------------------
__global__ void __launch_bounds__(256) mma_gemm(
    const __nv_bfloat16* __restrict__ Ah, const __nv_bfloat16* __restrict__ Al,
    const __nv_bfloat16* __restrict__ Wh, const __nv_bfloat16* __restrict__ Wl,
    const float* __restrict__ bias, float* __restrict__ C, int K)
{
    extern __shared__ char smc[];
    __shared__ float s_bias[64];

    const int tid = threadIdx.x;
    const int w   = tid >> 5;
    const int ln  = tid & 31;
    const int m0  = blockIdx.y << 7;
    const int n0  = blockIdx.x << 6;
    const int mw  = (w >> 1) << 5;
    const int nw  = (w & 1) << 5;

    if (tid < 64) s_bias[tid] = __ldg(&bias[n0 + tid]);

    const uint32_t ub = smem_u32(smc);

    int a_s[2]; size_t a_g[2];
#pragma unroll
    for (int i = 0; i < 2; i++) {
        int u  = tid + 256 * i;
        int ar = u >> 2, ac = u & 3;
        a_s[i] = ar * 64 + ((ac ^ ((ar >> 1) & 3)) << 4);
        a_g[i] = (size_t)(m0 + ar) * K + ac * 8;
    }
    const int wr  = tid >> 2, wc2 = tid & 3;
    const int w_s = wr * 64 + ((wc2 ^ ((wr >> 1) & 3)) << 4);
    const size_t w_g = (size_t)(n0 + wr) * K + wc2 * 8;

    const int arl  = (ln & 7) + ((ln >> 3) & 1) * 8;
    const int akh  = (ln >> 4) & 1;
    const int swzA = (arl >> 1) & 3;
    const int brl  = (ln & 7) + ((ln >> 4) & 1) * 8;
    const int bkh  = (ln >> 3) & 1;
    const int swzB = (brl >> 1) & 3;

    float acc[2][4][4];
#pragma unroll
    for (int mi = 0; mi < 2; mi++)
#pragma unroll
        for (int nj = 0; nj < 4; nj++)
#pragma unroll
            for (int q = 0; q < 4; q++) acc[mi][nj][q] = 0.0f;

    const int NC = K >> 5;

    {
        char* bp = smc;
#pragma unroll
        for (int i = 0; i < 2; i++) {
            uint4 vh = __ldg((const uint4*)(Ah + a_g[i]));
            uint4 vl = __ldg((const uint4*)(Al + a_g[i]));
            *(uint4*)(bp + a_s[i])        = vh;
            *(uint4*)(bp + 8192 + a_s[i]) = vl;
        }
        uint4 wh = __ldg((const uint4*)(Wh + w_g));
        uint4 wl = __ldg((const uint4*)(Wl + w_g));
        *(uint4*)(bp + 16384 + w_s) = wh;
        *(uint4*)(bp + 20480 + w_s) = wl;
    }
    __syncthreads();

    for (int c = 0; c < NC; c++) {
        uint4 rah[2], ral[2], rwh, rwl;
        if (c + 1 < NC) {
            size_t ko = (size_t)(c + 1) * 32;
#pragma unroll
            for (int i = 0; i < 2; i++) {
                rah[i] = __ldg((const uint4*)(Ah + a_g[i] + ko));
                ral[i] = __ldg((const uint4*)(Al + a_g[i] + ko));
            }
            rwh = __ldg((const uint4*)(Wh + w_g + ko));
            rwl = __ldg((const uint4*)(Wl + w_g + ko));
        }

        const uint32_t base = ub + (uint32_t)(c & 1) * MG_BUF;
#pragma unroll
        for (int s = 0; s < 2; s++) {
            uint32_t fah[2][4], fal[2][4], fbh[2][4], fbl[2][4];
#pragma unroll
            for (int mi = 0; mi < 2; mi++) {
                int row = mw + mi * 16 + arl;
                uint32_t off = row * 64 + (((2 * s + akh) ^ swzA) << 4);
                ldsm4(fah[mi], base + off);
                ldsm4(fal[mi], base + 8192 + off);
            }
#pragma unroll
            for (int nj2 = 0; nj2 < 2; nj2++) {
                int row = nw + nj2 * 16 + brl;
                uint32_t off = row * 64 + (((2 * s + bkh) ^ swzB) << 4);
                ldsm4(fbh[nj2], base + 16384 + off);
                ldsm4(fbl[nj2], base + 20480 + off);
            }
#pragma unroll
            for (int mi = 0; mi < 2; mi++)
#pragma unroll
                for (int nj2 = 0; nj2 < 2; nj2++)
#pragma unroll
                    for (int hh = 0; hh < 2; hh++) {
                        float* d = acc[mi][nj2 * 2 + hh];
                        mma_bf16(d, fah[mi], &fbh[nj2][hh * 2]);
                        mma_bf16(d, fal[mi], &fbh[nj2][hh * 2]);
                        mma_bf16(d, fah[mi], &fbl[nj2][hh * 2]);
                    }
        }

        if (c + 1 < NC) {
            char* bp = smc + ((c + 1) & 1) * MG_BUF;
#pragma unroll
            for (int i = 0; i < 2; i++) {
                *(uint4*)(bp + a_s[i])        = rah[i];
                *(uint4*)(bp + 8192 + a_s[i]) = ral[i];
            }
            *(uint4*)(bp + 16384 + w_s) = rwh;
            *(uint4*)(bp + 20480 + w_s) = rwl;
            __syncthreads();
        }
    }

    const int er = ln >> 2;
    const int ec = (ln & 3) * 2;
#pragma unroll
    for (int mi = 0; mi < 2; mi++) {
#pragma unroll
        for (int nj = 0; nj < 4; nj++) {
            int row = m0 + mw + mi * 16 + er;
            int cl  = nw + nj * 8 + ec;
            float b0 = s_bias[cl], b1 = s_bias[cl + 1];
            float2 o0 = make_float2(acc[mi][nj][0] + b0, acc[mi][nj][1] + b1);
            float2 o1 = make_float2(acc[mi][nj][2] + b0, acc[mi][nj][3] + b1);
            *(float2*)&C[(size_t)row * G + n0 + cl]       = o0;
            *(float2*)&C[(size_t)(row + 8) * G + n0 + cl] = o1;
        }
    }
}

// ------------------------- tensor-core recurrence (v5: fp16 2-term + scaled lo) -------------------------
// 128 CTAs (8 units x 32 batches). W_hh in fp16 hi + (lo * 1024); h staged as
// fp16 (2^-11 residual). Separate lo accumulator recombined *2^-10 at the
// partial write. Layer0 writes fp16 h (recurrence) AND bf16 hi/lo (layer1 GEMM).
__global__ void __launch_bounds__(512, 1) recur_tc(float* outArg, int layer)
{
    extern __shared__ char smraw[];
    char*  Whi = smraw;
    char*  Wlo = smraw + 32768;
    char*  Hf  = smraw + 65536;
    float* part = (float*)(smraw + RT_PART_OFF);   // [4 kq][32 row][34]

    const float* Whh = layer ? g_Whh1 : g_Whh0;
    const int tid = threadIdx.x;
    const int w   = tid >> 5;
    const int ln  = tid & 31;
    const int mh  = w >> 3;
    const int nh  = (w >> 2) & 1;
    const int kq  = w & 3;
    const int unit0 = (blockIdx.x >> 1) * 8;
    const int bh    = blockIdx.x & 1;
    const int bb0   = bh * 32;
    unsigned int* barp = &g_bar2[bh][0];

    // ---- convert + stage W_hh into swizzled SMEM (fp16 hi + scaled lo) ----
    for (int i = tid; i < 32 * 512; i += 512) {
        int r = i >> 9, k = i & 511;
        int u = r >> 2, g = r & 3;
        float v = __ldg(&Whh[(size_t)(g * H + unit0 + u) * H + k]);
        __half hi = __float2half(v);
        __half lo = __float2half((v - __half2float(hi)) * WLO_SCALE);
        int off = r * 1024 + (((k >> 3) ^ (r & 7)) << 4) + (k & 7) * 2;
        *(__half*)(Whi + off) = hi;
        *(__half*)(Wlo + off) = lo;
    }
    __syncthreads();

    // ---- ldmatrix lane constants (proven mapping) ----
    const int arl = (ln & 7) + ((ln >> 3) & 1) * 8;
    const int akh = (ln >> 4) & 1;
    const int brl = (ln & 7) + ((ln >> 4) & 1) * 8;
    const int bkh = (ln >> 3) & 1;
    const int rowA = mh * 16 + arl;
    const int rowB = nh * 16 + brl;
    const uint32_t baseWhi = smem_u32(Whi) + rowA * 1024;
    const uint32_t baseWlo = smem_u32(Wlo) + rowA * 1024;
    const uint32_t baseHf  = smem_u32(Hf)  + rowB * 1024;
    const int aX = rowA & 7;
    const int bX = rowB & 7;

    // ---- hoist W fragments into registers ----
    uint32_t wfh[8][4], wfl[8][4];
#pragma unroll
    for (int i = 0; i < 8; i++) {
        int c2 = (kq * 8 + i) * 2;
        uint32_t ca = (uint32_t)((c2 + akh) ^ aX) << 4;
        ldsm4(wfh[i], baseWhi + ca);
        ldsm4(wfl[i], baseWlo + ca);
    }

    const int er = ln >> 2;
    const int ec = (ln & 3) * 2;

    // staging roles: 32 rows x 64 uint4 -> 4 uint4/thread
    const int sb = tid >> 4;
    const int cj = tid & 15;
    const uint32_t stOff = sb * 1024;

    // activation roles (tid < 256)
    const int ul = tid >> 5;
    const int ab = tid & 31;
    float creg = 0.0f;

    float* outp = layer ? outArg : (float*)0;

    for (int t = 0; t < T; t++) {
        const __half* hin;
        if (layer == 0) hin = (t == 0) ? g_h1f16[0] : (g_Af16 + (size_t)(t - 1) * B * H);
        else            hin = g_h1f16[t & 1];
        const float* xwt = g_xW + (size_t)t * B * G;

        float xg0 = 0.f, xg1 = 0.f, xg2 = 0.f, xg3 = 0.f;
        if (tid < 256) {
            xg0 = __ldg(&xwt[(bb0 + ab) * G + 0 * H + unit0 + ul]);
            xg1 = __ldg(&xwt[(bb0 + ab) * G + 1 * H + unit0 + ul]);
            xg2 = __ldg(&xwt[(bb0 + ab) * G + 2 * H + unit0 + ul]);
            xg3 = __ldg(&xwt[(bb0 + ab) * G + 3 * H + unit0 + ul]);
        }

        // ---- stage h fp16 (32 b x 512 = 64 uint4/row), swizzled, one wave ----
        {
            const uint4* gh = (const uint4*)(hin + (size_t)(bb0 + sb) * H);
            uint4 v[4];
#pragma unroll
            for (int j = 0; j < 4; j++)
                v[j] = __ldcg(gh + cj + 16 * j);
#pragma unroll
            for (int j = 0; j < 4; j++) {
                int c4 = cj + 16 * j;
                *(uint4*)(Hf + stOff + ((c4 ^ (sb & 7)) << 4)) = v[j];
            }
        }
        __syncthreads();

        // ---- MMA: d += Wh*h ; dl += (Wl*1024)*h ----
        float d0[4] = {0, 0, 0, 0}, d1[4] = {0, 0, 0, 0};
        float e0[4] = {0, 0, 0, 0}, e1[4] = {0, 0, 0, 0};
#pragma unroll
        for (int i = 0; i < 8; i++) {
            int c2 = (kq * 8 + i) * 2;
            uint32_t fb[4];
            uint32_t cb = (uint32_t)((c2 + bkh) ^ bX) << 4;
            ldsm4(fb, baseHf + cb);
            mma_f16(d0, wfh[i], &fb[0]);
            mma_f16(d1, wfh[i], &fb[2]);
            mma_f16(e0, wfl[i], &fb[0]);
            mma_f16(e1, wfl[i], &fb[2]);
        }

        // ---- write partials (hi + lo*2^-10): part[kq][row][batch] ----
        {
            float* pb = part + kq * (32 * 34);
            int r0 = mh * 16 + er;
            int c0 = nh * 16 + ec;
            *(float2*)&pb[r0 * 34 + c0] =
                make_float2(d0[0] + e0[0] * WLO_INV, d0[1] + e0[1] * WLO_INV);
            *(float2*)&pb[(r0 + 8) * 34 + c0] =
                make_float2(d0[2] + e0[2] * WLO_INV, d0[3] + e0[3] * WLO_INV);
            *(float2*)&pb[r0 * 34 + c0 + 8] =
                make_float2(d1[0] + e1[0] * WLO_INV, d1[1] + e1[1] * WLO_INV);
            *(float2*)&pb[(r0 + 8) * 34 + c0 + 8] =
                make_float2(d1[2] + e1[2] * WLO_INV, d1[3] + e1[3] * WLO_INV);
        }
        __syncthreads();

        // ---- activation: thread = (unit ul, batch ab), tid < 256 ----
        if (tid < 256) {
            float gate[4];
#pragma unroll
            for (int g = 0; g < 4; g++) {
                int r = ul * 4 + g;
                gate[g] = part[0 * 32 * 34 + r * 34 + ab]
                        + part[1 * 32 * 34 + r * 34 + ab]
                        + part[2 * 32 * 34 + r * 34 + ab]
                        + part[3 * 32 * 34 + r * 34 + ab];
            }
            float gi = gate[0] + xg0, gf = gate[1] + xg1;
            float gg = gate[2] + xg2, go = gate[3] + xg3;
            creg = sigmf(gf) * creg + sigmf(gi) * __tanhf(gg);
            float hv = sigmf(go) * __tanhf(creg);

            __half hf = __float2half(hv);
            if (layer == 0) {
                size_t o = (size_t)(t * B + bb0 + ab) * H + unit0 + ul;
                st_u16_cg(&g_Af16[o], *(unsigned short*)&hf);
                // bf16 hi/lo for layer1's projection (3-term accuracy)
                __nv_bfloat16 bh16 = __float2bfloat16(hv);
                __nv_bfloat16 bl16 = __float2bfloat16(hv - __bfloat162float(bh16));
                st_u16_cg(&g_Ah[o], *(unsigned short*)&bh16);
                st_u16_cg(&g_Al[o], *(unsigned short*)&bl16);
            } else {
                size_t o = (size_t)(bb0 + ab) * H + unit0 + ul;
                st_u16_cg(&g_h1f16[(t + 1) & 1][o], *(unsigned short*)&hf);
                if (t == T - 1) outp[o] = hv;
            }
        }

        // ---- per-half grid barrier (64 CTAs) ----
        if (t + 1 < T) {
            __syncthreads();
            if (tid == 0) {
                unsigned int one = 1u;
                asm volatile("red.release.gpu.global.add.u32 [%0], %1;"
                             :: "l"(barp), "r"(one) : "memory");
                unsigned int want = (unsigned int)(t + 1) * 64u;
                unsigned int vv;
                do {
                    asm volatile("ld.acquire.gpu.global.u32 %0, [%1];"
                                 : "=r"(vv) : "l"(barp));
                } while (vv < want);
            }
            __syncthreads();
        }
    }
}

// ------------------------- launch -------------------------
extern "C" void kernel_launch(void* const* d_in, const int* in_sizes, int n_in,
                              void* d_out, int out_size)
{
    (void)in_sizes; (void)n_in; (void)out_size;
    const float* x = (const float*)d_in[0];

    cudaFuncSetAttribute(mma_gemm, cudaFuncAttributeMaxDynamicSharedMemorySize, MG_SMEM);
    cudaFuncSetAttribute(recur_tc, cudaFuncAttributeMaxDynamicSharedMemorySize, RT_SMEM);

    prep_kernel<<<512, 256>>>(
        (const float*)d_in[1],  (const float*)d_in[5],
        (const float*)d_in[2],  (const float*)d_in[6],
        (const float*)d_in[3],  (const float*)d_in[4],
        (const float*)d_in[7],  (const float*)d_in[11],
        (const float*)d_in[8],  (const float*)d_in[12],
        (const float*)d_in[9],  (const float*)d_in[10]);

    float* bias0; cudaGetSymbolAddress((void**)&bias0, g_bias0);
    float* bias1; cudaGetSymbolAddress((void**)&bias1, g_bias1);
    float* xW;    cudaGetSymbolAddress((void**)&xW,    g_xW);
    __nv_bfloat16 *Ah, *Al, *W0h, *W0l, *W1h, *W1l;
    cudaGetSymbolAddress((void**)&Ah,  g_Ah);
    cudaGetSymbolAddress((void**)&Al,  g_Al);
    cudaGetSymbolAddress((void**)&W0h, g_W0h);
    cudaGetSymbolAddress((void**)&W0l, g_W0l);
    cudaGetSymbolAddress((void**)&W1h, g_W1h);
    cudaGetSymbolAddress((void**)&W1l, g_W1l);

    dim3 mgrid(G / 64, (T * B) / 128);

    // layer 0
    convert_x<<<512, 256>>>(x);
    reset_state<<<(B * H + 255) / 256, 256>>>();
    mma_gemm<<<mgrid, 256, MG_SMEM>>>(Ah, Al, W0h, W0l, bias0, xW, DIN);
    recur_tc<<<NCTA, 512, RT_SMEM>>>((float*)0, 0);

    // layer 1 (g_Ah/g_Al hold layer0's h sequence in bf16 hi/lo)
    mma_gemm<<<mgrid, 256, MG_SMEM>>>(Ah, Al, W1h, W1l, bias1, xW, H);
    reset_state<<<(B * H + 255) / 256, 256>>>();
    recur_tc<<<NCTA, 512, RT_SMEM>>>((float*)d_out, 1);
}

// round 16
// speedup vs baseline: 1.2158x; 1.2158x over previous
#include <cuda_runtime.h>
#include <cuda_bf16.h>
#include <cuda_fp16.h>
#include <cstdint>

// Problem constants
#define B    64
#define T    512
#define DIN  256
#define H    512
#define G    2048   // 4*H

#define NCTA 128

// mma_gemm tile config (proven R8)
#define MG_BUF   24576
#define MG_SMEM  (2 * MG_BUF)

// recur_tc SMEM layout (bytes): Whi @0 | Wlo @32768 | Hf @65536 | part @98304
#define RT_PART_OFF 98304
#define RT_SMEM     (98304 + 4 * 32 * 34 * 4)   // 115712

// scale for the fp16 W lo-plane (avoids fp16 denormal flush)
#define WLO_SCALE    1024.0f
#define WLO_INV      (1.0f / 1024.0f)

typedef unsigned long long u64;

// ------------------------- device scratch -------------------------
__device__ float g_Whh0[G * H];
__device__ float g_Whh1[G * H];
__device__ float g_bias0[G];
__device__ float g_bias1[G];
__device__ float g_xW[(size_t)T * B * G];            // [t*B+b][G]
__device__ unsigned int g_bar2[2][16];               // per-half barrier counters (proven R6-R13)
// bf16 hi/lo activations for PROJECTION GEMMs: x, then layer0 h-sequence
__device__ __nv_bfloat16 g_Ah[(size_t)T * B * H];
__device__ __nv_bfloat16 g_Al[(size_t)T * B * H];
// fp16 h planes for the RECURRENCE
__device__ __half g_Af16[(size_t)T * B * H];         // layer0 h sequence (fp16)
__device__ __half g_h1f16[2][B * H];                 // layer1 double-buffered h; [0] = t=0 zeros
// masked+split input-projection weights (bf16, proven path)
__device__ __nv_bfloat16 g_W0h[G * DIN], g_W0l[G * DIN];
__device__ __nv_bfloat16 g_W1h[G * H],   g_W1l[G * H];

// ------------------------- helpers -------------------------
__device__ __forceinline__ float sigmf(float x) {
    return 1.0f / (1.0f + __expf(-x));
}
__device__ __forceinline__ uint32_t smem_u32(const void* p) {
    uint32_t a;
    asm("{ .reg .u64 t; cvta.to.shared.u64 t, %1; cvt.u32.u64 %0, t; }" : "=r"(a) : "l"(p));
    return a;
}
__device__ __forceinline__ void ldsm4(uint32_t* r, uint32_t addr) {
    asm volatile("ldmatrix.sync.aligned.m8n8.x4.shared.b16 {%0,%1,%2,%3}, [%4];"
                 : "=r"(r[0]), "=r"(r[1]), "=r"(r[2]), "=r"(r[3]) : "r"(addr));
}
// bf16 HMMA (projection GEMM)
__device__ __forceinline__ void mma_bf16(float* d, const uint32_t* a, const uint32_t* b) {
    asm volatile(
        "mma.sync.aligned.m16n8k16.row.col.f32.bf16.bf16.f32 "
        "{%0,%1,%2,%3}, {%4,%5,%6,%7}, {%8,%9}, {%0,%1,%2,%3};"
        : "+f"(d[0]), "+f"(d[1]), "+f"(d[2]), "+f"(d[3])
        : "r"(a[0]), "r"(a[1]), "r"(a[2]), "r"(a[3]), "r"(b[0]), "r"(b[1]));
}
// fp16 HMMA (recurrence)
__device__ __forceinline__ void mma_f16(float* d, const uint32_t* a, const uint32_t* b) {
    asm volatile(
        "mma.sync.aligned.m16n8k16.row.col.f32.f16.f16.f32 "
        "{%0,%1,%2,%3}, {%4,%5,%6,%7}, {%8,%9}, {%0,%1,%2,%3};"
        : "+f"(d[0]), "+f"(d[1]), "+f"(d[2]), "+f"(d[3])
        : "r"(a[0]), "r"(a[1]), "r"(a[2]), "r"(a[3]), "r"(b[0]), "r"(b[1]));
}
__device__ __forceinline__ void st_u16_cg(void* p, unsigned short u) {
    asm volatile("st.global.cg.u16 [%0], %1;" :: "l"(p), "h"(u) : "memory");
}

// ------------------------- prep -------------------------
__global__ void prep_kernel(const float* Wih0, const float* mih0,
                            const float* Whh0, const float* mhh0,
                            const float* bih0, const float* bhh0,
                            const float* Wih1, const float* mih1,
                            const float* Whh1, const float* mhh1,
                            const float* bih1, const float* bhh1)
{
    int idx0 = blockIdx.x * blockDim.x + threadIdx.x;
    int stride = gridDim.x * blockDim.x;
    for (int i = idx0; i < G * H; i += stride) g_Whh0[i] = Whh0[i] * mhh0[i];
    for (int i = idx0; i < G * H; i += stride) g_Whh1[i] = Whh1[i] * mhh1[i];
    for (int i = idx0; i < G * DIN; i += stride) {
        float v = Wih0[i] * mih0[i];
        __nv_bfloat16 h = __float2bfloat16(v);
        g_W0h[i] = h;
        g_W0l[i] = __float2bfloat16(v - __bfloat162float(h));
    }
    for (int i = idx0; i < G * H; i += stride) {
        float v = Wih1[i] * mih1[i];
        __nv_bfloat16 h = __float2bfloat16(v);
        g_W1h[i] = h;
        g_W1l[i] = __float2bfloat16(v - __bfloat162float(h));
    }
    for (int i = idx0; i < G; i += stride) {
        g_bias0[i] = bih0[i] + bhh0[i];
        g_bias1[i] = bih1[i] + bhh1[i];
    }
}

__global__ void reset_state() {
    int i = blockIdx.x * blockDim.x + threadIdx.x;
    if (i < B * H) {
        __half z = __float2half(0.0f);
        g_h1f16[0][i] = z; g_h1f16[1][i] = z;
    }
    if (i < 32) g_bar2[i >> 4][i & 15] = 0u;
}

// convert x [B,T,DIN] -> bf16 hi/lo [t*B+b][DIN]
__global__ void convert_x(const float* __restrict__ x) {
    int i = blockIdx.x * blockDim.x + threadIdx.x;
    int n = T * B * DIN;
    for (; i < n; i += gridDim.x * blockDim.x) {
        int m = i / DIN, k = i - m * DIN;
        int b = m & (B - 1), t = m >> 6;
        float v = x[(size_t)(b * T + t) * DIN + k];
        __nv_bfloat16 h = __float2bfloat16(v);
        g_Ah[i] = h;
        g_Al[i] = __float2bfloat16(v - __bfloat162float(h));
    }
}

// ------------------------- warp-MMA projection GEMM (proven R8, bf16 3-term) -------------------------
__global__ void __launch_bounds__(256) mma_gemm(
    const __nv_bfloat16* __restrict__ Ah, const __nv_bfloat16* __restrict__ Al,
    const __nv_bfloat16* __restrict__ Wh, const __nv_bfloat16* __restrict__ Wl,
    const float* __restrict__ bias, float* __restrict__ C, int K)
{
    extern __shared__ char smc[];
    __shared__ float s_bias[64];

    const int tid = threadIdx.x;
    const int w   = tid >> 5;
    const int ln  = tid & 31;
    const int m0  = blockIdx.y << 7;
    const int n0  = blockIdx.x << 6;
    const int mw  = (w >> 1) << 5;
    const int nw  = (w & 1) << 5;

    if (tid < 64) s_bias[tid] = __ldg(&bias[n0 + tid]);

    const uint32_t ub = smem_u32(smc);

    int a_s[2]; size_t a_g[2];
#pragma unroll
    for (int i = 0; i < 2; i++) {
        int u  = tid + 256 * i;
        int ar = u >> 2, ac = u & 3;
        a_s[i] = ar * 64 + ((ac ^ ((ar >> 1) & 3)) << 4);
        a_g[i] = (size_t)(m0 + ar) * K + ac * 8;
    }
    const int wr  = tid >> 2, wc2 = tid & 3;
    const int w_s = wr * 64 + ((wc2 ^ ((wr >> 1) & 3)) << 4);
    const size_t w_g = (size_t)(n0 + wr) * K + wc2 * 8;

    const int arl  = (ln & 7) + ((ln >> 3) & 1) * 8;
    const int akh  = (ln >> 4) & 1;
    const int swzA = (arl >> 1) & 3;
    const int brl  = (ln & 7) + ((ln >> 4) & 1) * 8;
    const int bkh  = (ln >> 3) & 1;
    const int swzB = (brl >> 1) & 3;

    float acc[2][4][4];
#pragma unroll
    for (int mi = 0; mi < 2; mi++)
#pragma unroll
        for (int nj = 0; nj < 4; nj++)
#pragma unroll
            for (int q = 0; q < 4; q++) acc[mi][nj][q] = 0.0f;

    const int NC = K >> 5;

    {
        char* bp = smc;
#pragma unroll
        for (int i = 0; i < 2; i++) {
            uint4 vh = __ldg((const uint4*)(Ah + a_g[i]));
            uint4 vl = __ldg((const uint4*)(Al + a_g[i]));
            *(uint4*)(bp + a_s[i])        = vh;
            *(uint4*)(bp + 8192 + a_s[i]) = vl;
        }
        uint4 wh = __ldg((const uint4*)(Wh + w_g));
        uint4 wl = __ldg((const uint4*)(Wl + w_g));
        *(uint4*)(bp + 16384 + w_s) = wh;
        *(uint4*)(bp + 20480 + w_s) = wl;
    }
    __syncthreads();

    for (int c = 0; c < NC; c++) {
        uint4 rah[2], ral[2], rwh, rwl;
        if (c + 1 < NC) {
            size_t ko = (size_t)(c + 1) * 32;
#pragma unroll
            for (int i = 0; i < 2; i++) {
                rah[i] = __ldg((const uint4*)(Ah + a_g[i] + ko));
                ral[i] = __ldg((const uint4*)(Al + a_g[i] + ko));
            }
            rwh = __ldg((const uint4*)(Wh + w_g + ko));
            rwl = __ldg((const uint4*)(Wl + w_g + ko));
        }

        const uint32_t base = ub + (uint32_t)(c & 1) * MG_BUF;
#pragma unroll
        for (int s = 0; s < 2; s++) {
            uint32_t fah[2][4], fal[2][4], fbh[2][4], fbl[2][4];
#pragma unroll
            for (int mi = 0; mi < 2; mi++) {
                int row = mw + mi * 16 + arl;
                uint32_t off = row * 64 + (((2 * s + akh) ^ swzA) << 4);
                ldsm4(fah[mi], base + off);
                ldsm4(fal[mi], base + 8192 + off);
            }
#pragma unroll
            for (int nj2 = 0; nj2 < 2; nj2++) {
                int row = nw + nj2 * 16 + brl;
                uint32_t off = row * 64 + (((2 * s + bkh) ^ swzB) << 4);
                ldsm4(fbh[nj2], base + 16384 + off);
                ldsm4(fbl[nj2], base + 20480 + off);
            }
#pragma unroll
            for (int mi = 0; mi < 2; mi++)
#pragma unroll
                for (int nj2 = 0; nj2 < 2; nj2++)
#pragma unroll
                    for (int hh = 0; hh < 2; hh++) {
                        float* d = acc[mi][nj2 * 2 + hh];
                        mma_bf16(d, fah[mi], &fbh[nj2][hh * 2]);
                        mma_bf16(d, fal[mi], &fbh[nj2][hh * 2]);
                        mma_bf16(d, fah[mi], &fbl[nj2][hh * 2]);
                    }
        }

        if (c + 1 < NC) {
            char* bp = smc + ((c + 1) & 1) * MG_BUF;
#pragma unroll
            for (int i = 0; i < 2; i++) {
                *(uint4*)(bp + a_s[i])        = rah[i];
                *(uint4*)(bp + 8192 + a_s[i]) = ral[i];
            }
            *(uint4*)(bp + 16384 + w_s) = rwh;
            *(uint4*)(bp + 20480 + w_s) = rwl;
            __syncthreads();
        }
    }

    const int er = ln >> 2;
    const int ec = (ln & 3) * 2;
#pragma unroll
    for (int mi = 0; mi < 2; mi++) {
#pragma unroll
        for (int nj = 0; nj < 4; nj++) {
            int row = m0 + mw + mi * 16 + er;
            int cl  = nw + nj * 8 + ec;
            float b0 = s_bias[cl], b1 = s_bias[cl + 1];
            float2 o0 = make_float2(acc[mi][nj][0] + b0, acc[mi][nj][1] + b1);
            float2 o1 = make_float2(acc[mi][nj][2] + b0, acc[mi][nj][3] + b1);
            *(float2*)&C[(size_t)row * G + n0 + cl]       = o0;
            *(float2*)&C[(size_t)(row + 8) * G + n0 + cl] = o1;
        }
    }
}

// ------------------------- tensor-core recurrence (v7: R13 + coalesced activation) -------------------------
// 128 CTAs (8 units x 32 batches). fp16 2-term split with scaled W-lo (R13).
// Counter barrier (proven). NEW: unit-major activation mapping (ul = tid&7)
// so the per-step h stores / xg loads coalesce into 16B runs instead of
// 1KB-strided scatter.
__global__ void __launch_bounds__(512, 1) recur_tc(float* outArg, int layer)
{
    extern __shared__ char smraw[];
    char*  Whi = smraw;
    char*  Wlo = smraw + 32768;
    char*  Hf  = smraw + 65536;
    float* part = (float*)(smraw + RT_PART_OFF);   // [4 kq][32 row][34]

    const float* Whh = layer ? g_Whh1 : g_Whh0;
    const int tid = threadIdx.x;
    const int w   = tid >> 5;
    const int ln  = tid & 31;
    const int mh  = w >> 3;
    const int nh  = (w >> 2) & 1;
    const int kq  = w & 3;
    const int unit0 = (blockIdx.x >> 1) * 8;
    const int bh    = blockIdx.x & 1;
    const int bb0   = bh * 32;
    unsigned int* barp = &g_bar2[bh][0];

    // ---- convert + stage W_hh into swizzled SMEM (fp16 hi + scaled lo) ----
    for (int i = tid; i < 32 * 512; i += 512) {
        int r = i >> 9, k = i & 511;
        int u = r >> 2, g = r & 3;
        float v = __ldg(&Whh[(size_t)(g * H + unit0 + u) * H + k]);
        __half hi = __float2half(v);
        __half lo = __float2half((v - __half2float(hi)) * WLO_SCALE);
        int off = r * 1024 + (((k >> 3) ^ (r & 7)) << 4) + (k & 7) * 2;
        *(__half*)(Whi + off) = hi;
        *(__half*)(Wlo + off) = lo;
    }
    __syncthreads();

    // ---- ldmatrix lane constants (proven mapping) ----
    const int arl = (ln & 7) + ((ln >> 3) & 1) * 8;
    const int akh = (ln >> 4) & 1;
    const int brl = (ln & 7) + ((ln >> 4) & 1) * 8;
    const int bkh = (ln >> 3) & 1;
    const int rowA = mh * 16 + arl;
    const int rowB = nh * 16 + brl;
    const uint32_t baseWhi = smem_u32(Whi) + rowA * 1024;
    const uint32_t baseWlo = smem_u32(Wlo) + rowA * 1024;
    const uint32_t baseHf  = smem_u32(Hf)  + rowB * 1024;
    const int aX = rowA & 7;
    const int bX = rowB & 7;

    // ---- hoist W fragments into registers ----
    uint32_t wfh[8][4], wfl[8][4];
#pragma unroll
    for (int i = 0; i < 8; i++) {
        int c2 = (kq * 8 + i) * 2;
        uint32_t ca = (uint32_t)((c2 + akh) ^ aX) << 4;
        ldsm4(wfh[i], baseWhi + ca);
        ldsm4(wfl[i], baseWlo + ca);
    }

    const int er = ln >> 2;
    const int ec = (ln & 3) * 2;

    // staging roles: 32 rows x 64 uint4 -> 4 uint4/thread
    const int sb = tid >> 4;
    const int cj = tid & 15;
    const uint32_t stOff = sb * 1024;

    // activation roles (tid < 256): UNIT-MAJOR for coalescing
    const int ul = tid & 7;             // unit 0..7 (consecutive lanes -> consecutive units)
    const int ab = tid >> 3;            // batch 0..31
    float creg = 0.0f;

    float* outp = layer ? outArg : (float*)0;

    for (int t = 0; t < T; t++) {
        const __half* hin;
        if (layer == 0) hin = (t == 0) ? g_h1f16[0] : (g_Af16 + (size_t)(t - 1) * B * H);
        else            hin = g_h1f16[t & 1];
        const float* xwt = g_xW + (size_t)t * B * G;

        float xg0 = 0.f, xg1 = 0.f, xg2 = 0.f, xg3 = 0.f;
        if (tid < 256) {
            xg0 = __ldg(&xwt[(bb0 + ab) * G + 0 * H + unit0 + ul]);
            xg1 = __ldg(&xwt[(bb0 + ab) * G + 1 * H + unit0 + ul]);
            xg2 = __ldg(&xwt[(bb0 + ab) * G + 2 * H + unit0 + ul]);
            xg3 = __ldg(&xwt[(bb0 + ab) * G + 3 * H + unit0 + ul]);
        }

        // ---- stage h fp16 (32 b x 512 = 64 uint4/row), swizzled, one wave ----
        {
            const uint4* gh = (const uint4*)(hin + (size_t)(bb0 + sb) * H);
            uint4 v[4];
#pragma unroll
            for (int j = 0; j < 4; j++)
                v[j] = __ldcg(gh + cj + 16 * j);
#pragma unroll
            for (int j = 0; j < 4; j++) {
                int c4 = cj + 16 * j;
                *(uint4*)(Hf + stOff + ((c4 ^ (sb & 7)) << 4)) = v[j];
            }
        }
        __syncthreads();

        // ---- MMA: d += Wh*h ; e += (Wl*1024)*h ----
        float d0[4] = {0, 0, 0, 0}, d1[4] = {0, 0, 0, 0};
        float e0[4] = {0, 0, 0, 0}, e1[4] = {0, 0, 0, 0};
#pragma unroll
        for (int i = 0; i < 8; i++) {
            int c2 = (kq * 8 + i) * 2;
            uint32_t fb[4];
            uint32_t cb = (uint32_t)((c2 + bkh) ^ bX) << 4;
            ldsm4(fb, baseHf + cb);
            mma_f16(d0, wfh[i], &fb[0]);
            mma_f16(d1, wfh[i], &fb[2]);
            mma_f16(e0, wfl[i], &fb[0]);
            mma_f16(e1, wfl[i], &fb[2]);
        }

        // ---- write partials (hi + lo*2^-10): part[kq][row][batch] ----
        {
            float* pb = part + kq * (32 * 34);
            int r0 = mh * 16 + er;
            int c0 = nh * 16 + ec;
            *(float2*)&pb[r0 * 34 + c0] =
                make_float2(d0[0] + e0[0] * WLO_INV, d0[1] + e0[1] * WLO_INV);
            *(float2*)&pb[(r0 + 8) * 34 + c0] =
                make_float2(d0[2] + e0[2] * WLO_INV, d0[3] + e0[3] * WLO_INV);
            *(float2*)&pb[r0 * 34 + c0 + 8] =
                make_float2(d1[0] + e1[0] * WLO_INV, d1[1] + e1[1] * WLO_INV);
            *(float2*)&pb[(r0 + 8) * 34 + c0 + 8] =
                make_float2(d1[2] + e1[2] * WLO_INV, d1[3] + e1[3] * WLO_INV);
        }
        __syncthreads();

        // ---- activation: thread = (unit ul, batch ab), tid < 256 ----
        if (tid < 256) {
            float gate[4];
#pragma unroll
            for (int g = 0; g < 4; g++) {
                int r = ul * 4 + g;
                gate[g] = part[0 * 32 * 34 + r * 34 + ab]
                        + part[1 * 32 * 34 + r * 34 + ab]
                        + part[2 * 32 * 34 + r * 34 + ab]
                        + part[3 * 32 * 34 + r * 34 + ab];
            }
            float gi = gate[0] + xg0, gf = gate[1] + xg1;
            float gg = gate[2] + xg2, go = gate[3] + xg3;
            creg = sigmf(gf) * creg + sigmf(gi) * __tanhf(gg);
            float hv = sigmf(go) * __tanhf(creg);

            __half hf = __float2half(hv);
            if (layer == 0) {
                size_t o = (size_t)(t * B + bb0 + ab) * H + unit0 + ul;
                st_u16_cg(&g_Af16[o], *(unsigned short*)&hf);
                __nv_bfloat16 bh16 = __float2bfloat16(hv);
                __nv_bfloat16 bl16 = __float2bfloat16(hv - __bfloat162float(bh16));
                st_u16_cg(&g_Ah[o], *(unsigned short*)&bh16);
                st_u16_cg(&g_Al[o], *(unsigned short*)&bl16);
            } else {
                size_t o = (size_t)(bb0 + ab) * H + unit0 + ul;
                st_u16_cg(&g_h1f16[(t + 1) & 1][o], *(unsigned short*)&hf);
                if (t == T - 1) outp[o] = hv;
            }
        }

        // ---- per-half counter barrier (proven R6-R13) ----
        if (t + 1 < T) {
            __syncthreads();
            if (tid == 0) {
                unsigned int one = 1u;
                asm volatile("red.release.gpu.global.add.u32 [%0], %1;"
                             :: "l"(barp), "r"(one) : "memory");
                unsigned int want = (unsigned int)(t + 1) * 64u;
                unsigned int vv;
                do {
                    asm volatile("ld.acquire.gpu.global.u32 %0, [%1];"
                                 : "=r"(vv) : "l"(barp));
                } while (vv < want);
            }
            __syncthreads();
        }
    }
}

// ------------------------- launch -------------------------
extern "C" void kernel_launch(void* const* d_in, const int* in_sizes, int n_in,
                              void* d_out, int out_size)
{
    (void)in_sizes; (void)n_in; (void)out_size;
    const float* x = (const float*)d_in[0];

    cudaFuncSetAttribute(mma_gemm, cudaFuncAttributeMaxDynamicSharedMemorySize, MG_SMEM);
    cudaFuncSetAttribute(recur_tc, cudaFuncAttributeMaxDynamicSharedMemorySize, RT_SMEM);

    prep_kernel<<<512, 256>>>(
        (const float*)d_in[1],  (const float*)d_in[5],
        (const float*)d_in[2],  (const float*)d_in[6],
        (const float*)d_in[3],  (const float*)d_in[4],
        (const float*)d_in[7],  (const float*)d_in[11],
        (const float*)d_in[8],  (const float*)d_in[12],
        (const float*)d_in[9],  (const float*)d_in[10]);

    float* bias0; cudaGetSymbolAddress((void**)&bias0, g_bias0);
    float* bias1; cudaGetSymbolAddress((void**)&bias1, g_bias1);
    float* xW;    cudaGetSymbolAddress((void**)&xW,    g_xW);
    __nv_bfloat16 *Ah, *Al, *W0h, *W0l, *W1h, *W1l;
    cudaGetSymbolAddress((void**)&Ah,  g_Ah);
    cudaGetSymbolAddress((void**)&Al,  g_Al);
    cudaGetSymbolAddress((void**)&W0h, g_W0h);
    cudaGetSymbolAddress((void**)&W0l, g_W0l);
    cudaGetSymbolAddress((void**)&W1h, g_W1h);
    cudaGetSymbolAddress((void**)&W1l, g_W1l);

    dim3 mgrid(G / 64, (T * B) / 128);

    // layer 0
    convert_x<<<512, 256>>>(x);
    reset_state<<<(B * H + 255) / 256, 256>>>();
    mma_gemm<<<mgrid, 256, MG_SMEM>>>(Ah, Al, W0h, W0l, bias0, xW, DIN);
    recur_tc<<<NCTA, 512, RT_SMEM>>>((float*)0, 0);

    // layer 1 (g_Ah/g_Al hold layer0's h sequence in bf16 hi/lo)
    mma_gemm<<<mgrid, 256, MG_SMEM>>>(Ah, Al, W1h, W1l, bias1, xW, H);
    reset_state<<<(B * H + 255) / 256, 256>>>();
    recur_tc<<<NCTA, 512, RT_SMEM>>>((float*)d_out, 1);
}